// round 1
// baseline (speedup 1.0000x reference)
#include <cuda_runtime.h>
#include <cuda_bf16.h>
#include <math.h>

// ---------------- problem constants ----------------
#define BATCH   32
#define IMG     224
#define PATCH   16
#define DIM     768
#define DEPTH   12
#define HEADS   12
#define SEQL    196            // (224/16)^2
#define MAXSEQ  128
#define MAXREP  16
#define DFF     3072
#define HD      64
#define MTOK    (BATCH * SEQL) // 6272 token rows

// ---------------- device scratch (no allocations allowed) ----------------
__device__ float g_xp   [MTOK * DIM];        // patchified input
__device__ float g_patch[MTOK * DIM];        // patch embedding (needed at end)
__device__ float g_h    [MTOK * DIM];        // residual stream
__device__ float g_qkv  [MTOK * 3 * DIM];    // qkv
__device__ float g_attn [MTOK * DIM];        // attention out (pre-proj)
__device__ float g_tmp  [MTOK * DIM];        // proj / mlp2 out
__device__ float g_ff   [(size_t)MTOK * DFF];// mlp hidden

// ---------------- patchify: x[B,3,224,224] -> xp[6272, 768] ----------------
__global__ void patchify_kernel(const float* __restrict__ x, float* __restrict__ xp)
{
    int idx = blockIdx.x * blockDim.x + threadIdx.x;
    if (idx >= MTOK * DIM) return;
    int row = idx / DIM;        // token
    int kk  = idx - row * DIM;  // feature
    int c   = kk >> 8;          // /256
    int r   = (kk >> 4) & 15;
    int col = kk & 15;
    int b   = row / SEQL;
    int s   = row - b * SEQL;
    int pr  = s / 14;
    int pc  = s - pr * 14;
    size_t xi = (((size_t)b * 3 + c) * IMG + (pr * PATCH + r)) * IMG + (pc * PATCH + col);
    xp[idx] = x[xi];
}

// ---------------- h = patch + pos (broadcast over batch) ----------------
__global__ void addpos_kernel(const float* __restrict__ patch, const float* __restrict__ pos,
                              float* __restrict__ h)
{
    int idx = blockIdx.x * blockDim.x + threadIdx.x;
    if (idx >= MTOK * DIM) return;
    int row = idx / DIM;
    int d   = idx - row * DIM;
    int s   = row % SEQL;
    h[idx] = patch[idx] + pos[s * DIM + d];
}

// ---------------- SGEMM: C[M,N] = A[M,K] @ B[K,N] + bias (opt gelu) --------
// BM=BN=128, BK=16, 256 threads, 8x8 micro-tiles. All dims divisible.
#define BM 128
#define BN 128
#define BKK 16

template<int GELU>
__global__ void __launch_bounds__(256, 2) sgemm_kernel(
    const float* __restrict__ A, const float* __restrict__ B,
    const float* __restrict__ bias, float* __restrict__ C,
    int N_, int K_)
{
    __shared__ float As[BKK][BM];
    __shared__ float Bs[BKK][BN];

    int tid = threadIdx.x;
    int tx  = tid & 15;           // 0..15 -> N
    int ty  = tid >> 4;           // 0..15 -> M
    int a_row0 = tid >> 2;        // 0..63
    int a_k4   = tid & 3;         // 0..3 (k group of 4)
    int b_row0 = tid >> 5;        // 0..7
    int b_c4   = tid & 31;        // 0..31

    const float* Ab = A + (size_t)blockIdx.y * BM * K_;
    const float* Bb = B + (size_t)blockIdx.x * BN;

    float acc[8][8];
#pragma unroll
    for (int i = 0; i < 8; i++)
#pragma unroll
        for (int j = 0; j < 8; j++) acc[i][j] = 0.f;

    for (int k0 = 0; k0 < K_; k0 += BKK) {
#pragma unroll
        for (int r = 0; r < 2; r++) {
            int row = a_row0 + r * 64;
            float4 v = *(const float4*)(Ab + (size_t)row * K_ + k0 + a_k4 * 4);
            As[a_k4 * 4 + 0][row] = v.x;
            As[a_k4 * 4 + 1][row] = v.y;
            As[a_k4 * 4 + 2][row] = v.z;
            As[a_k4 * 4 + 3][row] = v.w;
        }
#pragma unroll
        for (int r = 0; r < 2; r++) {
            int row = b_row0 + r * 8;
            *(float4*)(&Bs[row][b_c4 * 4]) =
                *(const float4*)(Bb + (size_t)(k0 + row) * N_ + b_c4 * 4);
        }
        __syncthreads();
#pragma unroll
        for (int k = 0; k < BKK; k++) {
            float4 a0 = *(const float4*)(&As[k][ty * 8]);
            float4 a1 = *(const float4*)(&As[k][ty * 8 + 4]);
            float4 b0 = *(const float4*)(&Bs[k][tx * 8]);
            float4 b1 = *(const float4*)(&Bs[k][tx * 8 + 4]);
            float av[8] = {a0.x, a0.y, a0.z, a0.w, a1.x, a1.y, a1.z, a1.w};
            float bv[8] = {b0.x, b0.y, b0.z, b0.w, b1.x, b1.y, b1.z, b1.w};
#pragma unroll
            for (int i = 0; i < 8; i++)
#pragma unroll
                for (int j = 0; j < 8; j++)
                    acc[i][j] = fmaf(av[i], bv[j], acc[i][j]);
        }
        __syncthreads();
    }

#pragma unroll
    for (int i = 0; i < 8; i++) {
        size_t row = (size_t)blockIdx.y * BM + ty * 8 + i;
#pragma unroll
        for (int j = 0; j < 8; j += 4) {
            int col = blockIdx.x * BN + tx * 8 + j;
            float4 v;
            v.x = acc[i][j + 0] + bias[col + 0];
            v.y = acc[i][j + 1] + bias[col + 1];
            v.z = acc[i][j + 2] + bias[col + 2];
            v.w = acc[i][j + 3] + bias[col + 3];
            if (GELU) {
                float* p = &v.x;
#pragma unroll
                for (int q = 0; q < 4; q++) {
                    float xx = p[q];
                    float inner = 0.7978845608028654f * (xx + 0.044715f * xx * xx * xx);
                    p[q] = 0.5f * xx * (1.f + tanhf(inner));
                }
            }
            *(float4*)(C + row * N_ + col) = v;
        }
    }
}

// ---------------- fused attention: one block per (b, head) -----------------
#define ACHUNK 64
__global__ void __launch_bounds__(224) attention_kernel(const float* __restrict__ qkv,
                                                        float* __restrict__ outp)
{
    __shared__ float Ks[ACHUNK][HD];
    __shared__ float Vs[ACHUNK][HD];
    int b  = blockIdx.x / HEADS;
    int hh = blockIdx.x % HEADS;
    int tid = threadIdx.x;
    const size_t base = (size_t)b * SEQL * (3 * DIM);

    float q[HD], o[HD];
    float m = -1e30f, l = 0.f;
    if (tid < SEQL) {
        const float* qp = qkv + base + (size_t)tid * (3 * DIM) + hh * HD;
#pragma unroll
        for (int d = 0; d < HD; d++) { q[d] = qp[d]; o[d] = 0.f; }
    }

    for (int kc = 0; kc < SEQL; kc += ACHUNK) {
        int len = min(ACHUNK, SEQL - kc);
        for (int i = tid; i < len * HD; i += 224) {
            int kr = i / HD, d = i - kr * HD;
            size_t src = base + (size_t)(kc + kr) * (3 * DIM) + hh * HD + d;
            Ks[kr][d] = qkv[src + DIM];
            Vs[kr][d] = qkv[src + 2 * DIM];
        }
        __syncthreads();
        if (tid < SEQL) {
            for (int k = 0; k < len; k++) {
                float s = 0.f;
#pragma unroll
                for (int d = 0; d < HD; d++) s = fmaf(q[d], Ks[k][d], s);
                s *= 0.125f;               // 1/sqrt(64)
                if (s > m) {
                    float corr = __expf(m - s);
                    l *= corr;
#pragma unroll
                    for (int d = 0; d < HD; d++) o[d] *= corr;
                    m = s;
                }
                float p = __expf(s - m);
                l += p;
#pragma unroll
                for (int d = 0; d < HD; d++) o[d] = fmaf(p, Vs[k][d], o[d]);
            }
        }
        __syncthreads();
    }
    if (tid < SEQL) {
        float inv = 1.f / l;
        float* op = outp + ((size_t)(b * SEQL + tid)) * DIM + hh * HD;
#pragma unroll
        for (int d = 0; d < HD; d++) op[d] = o[d] * inv;
    }
}

// ---------------- residual add + layernorm (in place on h) -----------------
__global__ void __launch_bounds__(256) add_ln_kernel(float* __restrict__ h,
                                                     const float* __restrict__ y,
                                                     const float* __restrict__ sc,
                                                     const float* __restrict__ bb)
{
    __shared__ float red1[8];
    __shared__ float red2[8];
    __shared__ float smean, srstd;
    int tok = blockIdx.x;
    int tid = threadIdx.x;
    const size_t off = (size_t)tok * DIM;

    float v[3];
#pragma unroll
    for (int i = 0; i < 3; i++) {
        int c = tid + i * 256;
        v[i] = h[off + c] + y[off + c];
    }
    float sum = v[0] + v[1] + v[2];
#pragma unroll
    for (int o = 16; o > 0; o >>= 1) sum += __shfl_xor_sync(0xffffffff, sum, o);
    if ((tid & 31) == 0) red1[tid >> 5] = sum;
    __syncthreads();
    if (tid == 0) {
        float x = 0.f;
#pragma unroll
        for (int i = 0; i < 8; i++) x += red1[i];
        smean = x * (1.f / DIM);
    }
    __syncthreads();
    float mean = smean;
    float sq = 0.f;
#pragma unroll
    for (int i = 0; i < 3; i++) { float d = v[i] - mean; sq += d * d; }
#pragma unroll
    for (int o = 16; o > 0; o >>= 1) sq += __shfl_xor_sync(0xffffffff, sq, o);
    if ((tid & 31) == 0) red2[tid >> 5] = sq;
    __syncthreads();
    if (tid == 0) {
        float x = 0.f;
#pragma unroll
        for (int i = 0; i < 8; i++) x += red2[i];
        srstd = rsqrtf(x * (1.f / DIM) + 1e-5f);
    }
    __syncthreads();
    float rstd = srstd;
#pragma unroll
    for (int i = 0; i < 3; i++) {
        int c = tid + i * 256;
        h[off + c] = (v[i] - mean) * rstd * sc[c] + bb[c];
    }
}

// ---------------- copy residual stream to out_state ------------------------
__global__ void copyout_kernel(const float* __restrict__ h, float* __restrict__ out)
{
    int idx = blockIdx.x * blockDim.x + threadIdx.x;
    if (idx < MTOK * DIM) out[idx] = h[idx];
}

// ---------------- repeat head + pack/gather: one block per batch -----------
__global__ void __launch_bounds__(256) head_kernel(const float* __restrict__ h,
                                                   const float* __restrict__ patch,
                                                   const float* __restrict__ rep_w,
                                                   const float* __restrict__ rep_b,
                                                   float* __restrict__ outq)
{
    __shared__ int cnt[SEQL];
    __shared__ int csum[SEQL];
    __shared__ int src[MAXSEQ];
    int b = blockIdx.x, tid = threadIdx.x;

    // argmax of logits == argmax of softmax: skip softmax entirely
    for (int s = tid; s < SEQL; s += 256) {
        const float* hr = h + ((size_t)(b * SEQL + s)) * DIM;
        float acc[MAXREP];
#pragma unroll
        for (int j = 0; j < MAXREP; j++) acc[j] = rep_b[j];
        for (int kk = 0; kk < DIM; kk++) {
            float hv = hr[kk];
            const float* wr = rep_w + kk * MAXREP;
#pragma unroll
            for (int j = 0; j < MAXREP; j++) acc[j] = fmaf(hv, wr[j], acc[j]);
        }
        int bi = 0; float bv = acc[0];
#pragma unroll
        for (int j = 1; j < MAXREP; j++) if (acc[j] > bv) { bv = acc[j]; bi = j; }
        cnt[s] = bi;   // first-max tie rule matches jnp.argmax
    }
    __syncthreads();
    if (tid == 0) {
        int r = 0;
        for (int i = 0; i < SEQL; i++) { r += cnt[i]; csum[i] = r; }
    }
    __syncthreads();
    int total = csum[SEQL - 1];
    if (tid < MAXSEQ) {
        int t = tid;
        int idx = SEQL;   // searchsorted 'right': smallest j with csum[j] > t
        for (int j = 0; j < SEQL; j++) if (csum[j] > t) { idx = j; break; }
        src[t] = (t < total) ? min(idx, SEQL - 1) : -1;
    }
    __syncthreads();
    for (int i = tid; i < MAXSEQ * DIM; i += 256) {
        int t = i / DIM, d = i - t * DIM;
        int si = src[t];
        float v = (si >= 0) ? patch[((size_t)(b * SEQL + si)) * DIM + d] : 0.f;
        outq[((size_t)(b * MAXSEQ + t)) * DIM + d] = v;
    }
}

// ---------------- launch ----------------------------------------------------
extern "C" void kernel_launch(void* const* d_in, const int* in_sizes, int n_in,
                              void* d_out, int out_size)
{
    const float* x       = (const float*)d_in[0];
    const float* patch_w = (const float*)d_in[1];
    const float* patch_b = (const float*)d_in[2];
    const float* pos     = (const float*)d_in[3];
    const float* Wqkv    = (const float*)d_in[4];
    const float* bqkv    = (const float*)d_in[5];
    const float* Wo      = (const float*)d_in[6];
    const float* bo      = (const float*)d_in[7];
    const float* ln1_s   = (const float*)d_in[8];
    const float* ln1_b   = (const float*)d_in[9];
    const float* W1      = (const float*)d_in[10];
    const float* b1      = (const float*)d_in[11];
    const float* W2      = (const float*)d_in[12];
    const float* b2      = (const float*)d_in[13];
    const float* ln2_s   = (const float*)d_in[14];
    const float* ln2_b   = (const float*)d_in[15];
    const float* rep_w   = (const float*)d_in[16];
    const float* rep_b   = (const float*)d_in[17];
    float* out = (float*)d_out;

    float *xp, *patch, *h, *qkv, *attn, *tmp, *ff;
    cudaGetSymbolAddress((void**)&xp,    g_xp);
    cudaGetSymbolAddress((void**)&patch, g_patch);
    cudaGetSymbolAddress((void**)&h,     g_h);
    cudaGetSymbolAddress((void**)&qkv,   g_qkv);
    cudaGetSymbolAddress((void**)&attn,  g_attn);
    cudaGetSymbolAddress((void**)&tmp,   g_tmp);
    cudaGetSymbolAddress((void**)&ff,    g_ff);

    const int EL = MTOK * DIM;
    const int TB = 256;

    patchify_kernel<<<(EL + TB - 1) / TB, TB>>>(x, xp);

    // patch embedding: [6272,768] @ [768,768] + b
    sgemm_kernel<0><<<dim3(DIM / BN, MTOK / BM), 256>>>(xp, patch_w, patch_b, patch, DIM, DIM);
    addpos_kernel<<<(EL + TB - 1) / TB, TB>>>(patch, pos, h);

    for (int l = 0; l < DEPTH; l++) {
        // qkv: [6272,768] @ [768,2304]
        sgemm_kernel<0><<<dim3((3 * DIM) / BN, MTOK / BM), 256>>>(
            h, Wqkv + (size_t)l * DIM * 3 * DIM, bqkv + (size_t)l * 3 * DIM, qkv, 3 * DIM, DIM);
        // attention
        attention_kernel<<<BATCH * HEADS, 224>>>(qkv, attn);
        // out proj: [6272,768] @ [768,768]
        sgemm_kernel<0><<<dim3(DIM / BN, MTOK / BM), 256>>>(
            attn, Wo + (size_t)l * DIM * DIM, bo + (size_t)l * DIM, tmp, DIM, DIM);
        add_ln_kernel<<<MTOK, 256>>>(h, tmp, ln1_s + (size_t)l * DIM, ln1_b + (size_t)l * DIM);
        // mlp1 + gelu: [6272,768] @ [768,3072]
        sgemm_kernel<1><<<dim3(DFF / BN, MTOK / BM), 256>>>(
            h, W1 + (size_t)l * DIM * DFF, b1 + (size_t)l * DFF, ff, DFF, DIM);
        // mlp2: [6272,3072] @ [3072,768]
        sgemm_kernel<0><<<dim3(DIM / BN, MTOK / BM), 256>>>(
            ff, W2 + (size_t)l * DFF * DIM, b2 + (size_t)l * DIM, tmp, DIM, DFF);
        add_ln_kernel<<<MTOK, 256>>>(h, tmp, ln2_s + (size_t)l * DIM, ln2_b + (size_t)l * DIM);
    }

    // outputs: out_state [32,196,768] then query [32,128,768]
    copyout_kernel<<<(EL + TB - 1) / TB, TB>>>(h, out);
    head_kernel<<<BATCH, 256>>>(h, patch, rep_w, rep_b, out + (size_t)MTOK * DIM);
}

// round 2
// speedup vs baseline: 1.0031x; 1.0031x over previous
#include <cuda_runtime.h>
#include <cuda_bf16.h>
#include <math.h>

// ---------------- problem constants ----------------
#define BATCH   32
#define IMG     224
#define PATCH   16
#define DIM     768
#define DEPTH   12
#define HEADS   12
#define SEQL    196            // (224/16)^2
#define MAXSEQ  128
#define MAXREP  16
#define DFF     3072
#define HD      64
#define MTOK    (BATCH * SEQL) // 6272 token rows

// ---------------- device scratch (no allocations allowed) ----------------
__device__ float g_xp   [MTOK * DIM];        // patchified input
__device__ float g_patch[MTOK * DIM];        // patch embedding (needed at end)
__device__ float g_h    [MTOK * DIM];        // residual stream
__device__ float g_qkv  [MTOK * 3 * DIM];    // qkv
__device__ float g_attn [MTOK * DIM];        // attention out (pre-proj)
__device__ float g_tmp  [MTOK * DIM];        // proj / mlp2 out
__device__ float g_ff   [(size_t)MTOK * DFF];// mlp hidden

// ---------------- patchify: x[B,3,224,224] -> xp[6272, 768] ----------------
__global__ void patchify_kernel(const float* __restrict__ x, float* __restrict__ xp)
{
    int idx = blockIdx.x * blockDim.x + threadIdx.x;
    if (idx >= MTOK * DIM) return;
    int row = idx / DIM;        // token
    int kk  = idx - row * DIM;  // feature
    int c   = kk >> 8;          // /256
    int r   = (kk >> 4) & 15;
    int col = kk & 15;
    int b   = row / SEQL;
    int s   = row - b * SEQL;
    int pr  = s / 14;
    int pc  = s - pr * 14;
    size_t xi = (((size_t)b * 3 + c) * IMG + (pr * PATCH + r)) * IMG + (pc * PATCH + col);
    xp[idx] = x[xi];
}

// ---------------- h = patch + pos (broadcast over batch) ----------------
__global__ void addpos_kernel(const float* __restrict__ patch, const float* __restrict__ pos,
                              float* __restrict__ h)
{
    int idx = blockIdx.x * blockDim.x + threadIdx.x;
    if (idx >= MTOK * DIM) return;
    int row = idx / DIM;
    int d   = idx - row * DIM;
    int s   = row % SEQL;
    h[idx] = patch[idx] + pos[s * DIM + d];
}

// ---------------- SGEMM: C[M,N] = A[M,K] @ B[K,N] + bias (opt gelu) --------
// BM=BN=128, BK=16, 256 threads, 8x8 micro-tiles. All dims divisible.
#define BM 128
#define BN 128
#define BKK 16

template<int GELU>
__global__ void __launch_bounds__(256, 2) sgemm_kernel(
    const float* __restrict__ A, const float* __restrict__ B,
    const float* __restrict__ bias, float* __restrict__ C,
    int N_, int K_)
{
    __shared__ float As[BKK][BM];
    __shared__ float Bs[BKK][BN];

    int tid = threadIdx.x;
    int tx  = tid & 15;           // 0..15 -> N
    int ty  = tid >> 4;           // 0..15 -> M
    int a_row0 = tid >> 2;        // 0..63
    int a_k4   = tid & 3;         // 0..3 (k group of 4)
    int b_row0 = tid >> 5;        // 0..7
    int b_c4   = tid & 31;        // 0..31

    const float* Ab = A + (size_t)blockIdx.y * BM * K_;
    const float* Bb = B + (size_t)blockIdx.x * BN;

    float acc[8][8];
#pragma unroll
    for (int i = 0; i < 8; i++)
#pragma unroll
        for (int j = 0; j < 8; j++) acc[i][j] = 0.f;

    for (int k0 = 0; k0 < K_; k0 += BKK) {
#pragma unroll
        for (int r = 0; r < 2; r++) {
            int row = a_row0 + r * 64;
            float4 v = *(const float4*)(Ab + (size_t)row * K_ + k0 + a_k4 * 4);
            As[a_k4 * 4 + 0][row] = v.x;
            As[a_k4 * 4 + 1][row] = v.y;
            As[a_k4 * 4 + 2][row] = v.z;
            As[a_k4 * 4 + 3][row] = v.w;
        }
#pragma unroll
        for (int r = 0; r < 2; r++) {
            int row = b_row0 + r * 8;
            *(float4*)(&Bs[row][b_c4 * 4]) =
                *(const float4*)(Bb + (size_t)(k0 + row) * N_ + b_c4 * 4);
        }
        __syncthreads();
#pragma unroll
        for (int k = 0; k < BKK; k++) {
            float4 a0 = *(const float4*)(&As[k][ty * 8]);
            float4 a1 = *(const float4*)(&As[k][ty * 8 + 4]);
            float4 b0 = *(const float4*)(&Bs[k][tx * 8]);
            float4 b1 = *(const float4*)(&Bs[k][tx * 8 + 4]);
            float av[8] = {a0.x, a0.y, a0.z, a0.w, a1.x, a1.y, a1.z, a1.w};
            float bv[8] = {b0.x, b0.y, b0.z, b0.w, b1.x, b1.y, b1.z, b1.w};
#pragma unroll
            for (int i = 0; i < 8; i++)
#pragma unroll
                for (int j = 0; j < 8; j++)
                    acc[i][j] = fmaf(av[i], bv[j], acc[i][j]);
        }
        __syncthreads();
    }

#pragma unroll
    for (int i = 0; i < 8; i++) {
        size_t row = (size_t)blockIdx.y * BM + ty * 8 + i;
#pragma unroll
        for (int j = 0; j < 8; j += 4) {
            int col = blockIdx.x * BN + tx * 8 + j;
            float4 v;
            v.x = acc[i][j + 0] + bias[col + 0];
            v.y = acc[i][j + 1] + bias[col + 1];
            v.z = acc[i][j + 2] + bias[col + 2];
            v.w = acc[i][j + 3] + bias[col + 3];
            if (GELU) {
                float* p = &v.x;
#pragma unroll
                for (int q = 0; q < 4; q++) {
                    float xx = p[q];
                    float inner = 0.7978845608028654f * (xx + 0.044715f * xx * xx * xx);
                    p[q] = 0.5f * xx * (1.f + tanhf(inner));
                }
            }
            *(float4*)(C + row * N_ + col) = v;
        }
    }
}

// ---------------- fused attention: one block per (b, head) -----------------
#define ACHUNK 64
__global__ void __launch_bounds__(224) attention_kernel(const float* __restrict__ qkv,
                                                        float* __restrict__ outp)
{
    __shared__ float Ks[ACHUNK][HD];
    __shared__ float Vs[ACHUNK][HD];
    int b  = blockIdx.x / HEADS;
    int hh = blockIdx.x % HEADS;
    int tid = threadIdx.x;
    const size_t base = (size_t)b * SEQL * (3 * DIM);

    float q[HD], o[HD];
    float m = -1e30f, l = 0.f;
    if (tid < SEQL) {
        const float* qp = qkv + base + (size_t)tid * (3 * DIM) + hh * HD;
#pragma unroll
        for (int d = 0; d < HD; d++) { q[d] = qp[d]; o[d] = 0.f; }
    }

    for (int kc = 0; kc < SEQL; kc += ACHUNK) {
        int len = min(ACHUNK, SEQL - kc);
        for (int i = tid; i < len * HD; i += 224) {
            int kr = i / HD, d = i - kr * HD;
            size_t src = base + (size_t)(kc + kr) * (3 * DIM) + hh * HD + d;
            Ks[kr][d] = qkv[src + DIM];
            Vs[kr][d] = qkv[src + 2 * DIM];
        }
        __syncthreads();
        if (tid < SEQL) {
            for (int k = 0; k < len; k++) {
                float s = 0.f;
#pragma unroll
                for (int d = 0; d < HD; d++) s = fmaf(q[d], Ks[k][d], s);
                s *= 0.125f;               // 1/sqrt(64)
                if (s > m) {
                    float corr = __expf(m - s);
                    l *= corr;
#pragma unroll
                    for (int d = 0; d < HD; d++) o[d] *= corr;
                    m = s;
                }
                float p = __expf(s - m);
                l += p;
#pragma unroll
                for (int d = 0; d < HD; d++) o[d] = fmaf(p, Vs[k][d], o[d]);
            }
        }
        __syncthreads();
    }
    if (tid < SEQL) {
        float inv = 1.f / l;
        float* op = outp + ((size_t)(b * SEQL + tid)) * DIM + hh * HD;
#pragma unroll
        for (int d = 0; d < HD; d++) op[d] = o[d] * inv;
    }
}

// ---------------- residual add + layernorm (in place on h) -----------------
__global__ void __launch_bounds__(256) add_ln_kernel(float* __restrict__ h,
                                                     const float* __restrict__ y,
                                                     const float* __restrict__ sc,
                                                     const float* __restrict__ bb)
{
    __shared__ float red1[8];
    __shared__ float red2[8];
    __shared__ float smean, srstd;
    int tok = blockIdx.x;
    int tid = threadIdx.x;
    const size_t off = (size_t)tok * DIM;

    float v[3];
#pragma unroll
    for (int i = 0; i < 3; i++) {
        int c = tid + i * 256;
        v[i] = h[off + c] + y[off + c];
    }
    float sum = v[0] + v[1] + v[2];
#pragma unroll
    for (int o = 16; o > 0; o >>= 1) sum += __shfl_xor_sync(0xffffffff, sum, o);
    if ((tid & 31) == 0) red1[tid >> 5] = sum;
    __syncthreads();
    if (tid == 0) {
        float x = 0.f;
#pragma unroll
        for (int i = 0; i < 8; i++) x += red1[i];
        smean = x * (1.f / DIM);
    }
    __syncthreads();
    float mean = smean;
    float sq = 0.f;
#pragma unroll
    for (int i = 0; i < 3; i++) { float d = v[i] - mean; sq += d * d; }
#pragma unroll
    for (int o = 16; o > 0; o >>= 1) sq += __shfl_xor_sync(0xffffffff, sq, o);
    if ((tid & 31) == 0) red2[tid >> 5] = sq;
    __syncthreads();
    if (tid == 0) {
        float x = 0.f;
#pragma unroll
        for (int i = 0; i < 8; i++) x += red2[i];
        srstd = rsqrtf(x * (1.f / DIM) + 1e-5f);
    }
    __syncthreads();
    float rstd = srstd;
#pragma unroll
    for (int i = 0; i < 3; i++) {
        int c = tid + i * 256;
        h[off + c] = (v[i] - mean) * rstd * sc[c] + bb[c];
    }
}

// ---------------- copy residual stream to out_state ------------------------
__global__ void copyout_kernel(const float* __restrict__ h, float* __restrict__ out)
{
    int idx = blockIdx.x * blockDim.x + threadIdx.x;
    if (idx < MTOK * DIM) out[idx] = h[idx];
}

// ---------------- repeat head + pack/gather: one block per batch -----------
__global__ void __launch_bounds__(256) head_kernel(const float* __restrict__ h,
                                                   const float* __restrict__ patch,
                                                   const float* __restrict__ rep_w,
                                                   const float* __restrict__ rep_b,
                                                   float* __restrict__ outq)
{
    __shared__ int cnt[SEQL];
    __shared__ int csum[SEQL];
    __shared__ int src[MAXSEQ];
    int b = blockIdx.x, tid = threadIdx.x;

    // argmax of logits == argmax of softmax: skip softmax entirely
    for (int s = tid; s < SEQL; s += 256) {
        const float* hr = h + ((size_t)(b * SEQL + s)) * DIM;
        float acc[MAXREP];
#pragma unroll
        for (int j = 0; j < MAXREP; j++) acc[j] = rep_b[j];
        for (int kk = 0; kk < DIM; kk++) {
            float hv = hr[kk];
            const float* wr = rep_w + kk * MAXREP;
#pragma unroll
            for (int j = 0; j < MAXREP; j++) acc[j] = fmaf(hv, wr[j], acc[j]);
        }
        int bi = 0; float bv = acc[0];
#pragma unroll
        for (int j = 1; j < MAXREP; j++) if (acc[j] > bv) { bv = acc[j]; bi = j; }
        cnt[s] = bi;   // first-max tie rule matches jnp.argmax
    }
    __syncthreads();
    if (tid == 0) {
        int r = 0;
        for (int i = 0; i < SEQL; i++) { r += cnt[i]; csum[i] = r; }
    }
    __syncthreads();
    int total = csum[SEQL - 1];
    if (tid < MAXSEQ) {
        int t = tid;
        int idx = SEQL;   // searchsorted 'right': smallest j with csum[j] > t
        for (int j = 0; j < SEQL; j++) if (csum[j] > t) { idx = j; break; }
        src[t] = (t < total) ? min(idx, SEQL - 1) : -1;
    }
    __syncthreads();
    for (int i = tid; i < MAXSEQ * DIM; i += 256) {
        int t = i / DIM, d = i - t * DIM;
        int si = src[t];
        float v = (si >= 0) ? patch[((size_t)(b * SEQL + si)) * DIM + d] : 0.f;
        outq[((size_t)(b * MAXSEQ + t)) * DIM + d] = v;
    }
}

// ---------------- launch ----------------------------------------------------
extern "C" void kernel_launch(void* const* d_in, const int* in_sizes, int n_in,
                              void* d_out, int out_size)
{
    const float* x       = (const float*)d_in[0];
    const float* patch_w = (const float*)d_in[1];
    const float* patch_b = (const float*)d_in[2];
    const float* pos     = (const float*)d_in[3];
    const float* Wqkv    = (const float*)d_in[4];
    const float* bqkv    = (const float*)d_in[5];
    const float* Wo      = (const float*)d_in[6];
    const float* bo      = (const float*)d_in[7];
    const float* ln1_s   = (const float*)d_in[8];
    const float* ln1_b   = (const float*)d_in[9];
    const float* W1      = (const float*)d_in[10];
    const float* b1      = (const float*)d_in[11];
    const float* W2      = (const float*)d_in[12];
    const float* b2      = (const float*)d_in[13];
    const float* ln2_s   = (const float*)d_in[14];
    const float* ln2_b   = (const float*)d_in[15];
    const float* rep_w   = (const float*)d_in[16];
    const float* rep_b   = (const float*)d_in[17];
    float* out = (float*)d_out;

    float *xp, *patch, *h, *qkv, *attn, *tmp, *ff;
    cudaGetSymbolAddress((void**)&xp,    g_xp);
    cudaGetSymbolAddress((void**)&patch, g_patch);
    cudaGetSymbolAddress((void**)&h,     g_h);
    cudaGetSymbolAddress((void**)&qkv,   g_qkv);
    cudaGetSymbolAddress((void**)&attn,  g_attn);
    cudaGetSymbolAddress((void**)&tmp,   g_tmp);
    cudaGetSymbolAddress((void**)&ff,    g_ff);

    const int EL = MTOK * DIM;
    const int TB = 256;

    patchify_kernel<<<(EL + TB - 1) / TB, TB>>>(x, xp);

    // patch embedding: [6272,768] @ [768,768] + b
    sgemm_kernel<0><<<dim3(DIM / BN, MTOK / BM), 256>>>(xp, patch_w, patch_b, patch, DIM, DIM);
    addpos_kernel<<<(EL + TB - 1) / TB, TB>>>(patch, pos, h);

    for (int l = 0; l < DEPTH; l++) {
        // qkv: [6272,768] @ [768,2304]
        sgemm_kernel<0><<<dim3((3 * DIM) / BN, MTOK / BM), 256>>>(
            h, Wqkv + (size_t)l * DIM * 3 * DIM, bqkv + (size_t)l * 3 * DIM, qkv, 3 * DIM, DIM);
        // attention
        attention_kernel<<<BATCH * HEADS, 224>>>(qkv, attn);
        // out proj: [6272,768] @ [768,768]
        sgemm_kernel<0><<<dim3(DIM / BN, MTOK / BM), 256>>>(
            attn, Wo + (size_t)l * DIM * DIM, bo + (size_t)l * DIM, tmp, DIM, DIM);
        add_ln_kernel<<<MTOK, 256>>>(h, tmp, ln1_s + (size_t)l * DIM, ln1_b + (size_t)l * DIM);
        // mlp1 + gelu: [6272,768] @ [768,3072]
        sgemm_kernel<1><<<dim3(DFF / BN, MTOK / BM), 256>>>(
            h, W1 + (size_t)l * DIM * DFF, b1 + (size_t)l * DFF, ff, DFF, DIM);
        // mlp2: [6272,3072] @ [3072,768]
        sgemm_kernel<0><<<dim3(DIM / BN, MTOK / BM), 256>>>(
            ff, W2 + (size_t)l * DFF * DIM, b2 + (size_t)l * DIM, tmp, DIM, DFF);
        add_ln_kernel<<<MTOK, 256>>>(h, tmp, ln2_s + (size_t)l * DIM, ln2_b + (size_t)l * DIM);
    }

    // outputs: out_state [32,196,768] then query [32,128,768]
    copyout_kernel<<<(EL + TB - 1) / TB, TB>>>(h, out);
    head_kernel<<<BATCH, 256>>>(h, patch, rep_w, rep_b, out + (size_t)MTOK * DIM);
}

// round 7
// speedup vs baseline: 1.5195x; 1.5148x over previous
#include <cuda_runtime.h>
#include <cuda_fp16.h>
#include <cuda_pipeline.h>
#include <mma.h>
#include <math.h>
#include <cstdint>

using namespace nvcuda;

#define BATCH 32
#define IMG 224
#define PATCH 16
#define DIM 768
#define DEPTH 12
#define HEADS 12
#define SEQL 196
#define MAXSEQ 128
#define MAXREP 16
#define DFF 3072
#define HD 64
#define MTOK (BATCH * SEQL)

// ---------------- scratch ----------------
__device__ float g_patch[MTOK * DIM];
__device__ float g_h    [MTOK * DIM];
__device__ float g_qkv  [MTOK * 3 * DIM];
__device__ float g_tmp  [MTOK * DIM];
// split activations: [row][2K] = [hi(K) | lo(K)]
__device__ __half g_xs [MTOK * 2 * DIM];
__device__ __half g_hs [MTOK * 2 * DIM];
__device__ __half g_ats[MTOK * 2 * DIM];
__device__ __half g_ffs[(size_t)MTOK * 2 * DFF];
// split transposed weights: [l][N][2K] = [hi(K) | lo(K)]
__device__ __half g_pws[DIM * 2 * DIM];
__device__ __half g_wqs[(size_t)DEPTH * 3 * DIM * 2 * DIM];
__device__ __half g_wos[(size_t)DEPTH * DIM * 2 * DIM];
__device__ __half g_w1s[(size_t)DEPTH * DFF * 2 * DIM];
__device__ __half g_w2s[(size_t)DEPTH * DIM * 2 * DFF];

__device__ __forceinline__ void h2split(float v, __half& hi, __half& lo) {
    hi = __float2half_rn(v);
    lo = __float2half_rn(v - __half2float(hi));
}

// ---------------- elementwise producers ----------------
__global__ void patchify_kernel(const float* __restrict__ x, __half* __restrict__ xs)
{
    int idx = blockIdx.x * blockDim.x + threadIdx.x;
    if (idx >= MTOK * DIM) return;
    int row = idx / DIM, kk = idx - row * DIM;
    int c = kk >> 8, r = (kk >> 4) & 15, col = kk & 15;
    int b = row / SEQL, s = row - b * SEQL;
    int pr = s / 14, pc = s - pr * 14;
    size_t xi = (((size_t)b * 3 + c) * IMG + (pr * PATCH + r)) * IMG + (pc * PATCH + col);
    __half hi, lo; h2split(x[xi], hi, lo);
    size_t base = (size_t)row * 2 * DIM + kk;
    xs[base] = hi; xs[base + DIM] = lo;
}

__global__ void addpos_kernel(const float* __restrict__ patch, const float* __restrict__ pos,
                              float* __restrict__ h, __half* __restrict__ hs)
{
    int idx = blockIdx.x * blockDim.x + threadIdx.x;
    if (idx >= MTOK * DIM) return;
    int row = idx / DIM, d = idx - row * DIM, s = row % SEQL;
    float v = patch[idx] + pos[s * DIM + d];
    h[idx] = v;
    __half hi, lo; h2split(v, hi, lo);
    size_t base = (size_t)row * 2 * DIM + d;
    hs[base] = hi; hs[base + DIM] = lo;
}

// W[l][K][N] -> Ws[l][N][2K] (hi | lo)
__global__ void wsplit_kernel(const float* __restrict__ W, __half* __restrict__ Ws, int K_, int N_)
{
    __shared__ float t[32][33];
    int l = blockIdx.z;
    const float* Wl = W + (size_t)l * K_ * N_;
    __half* Wsl = Ws + (size_t)l * N_ * 2 * K_;
    int n0 = blockIdx.x * 32, k0 = blockIdx.y * 32;
    int tx = threadIdx.x, ty = threadIdx.y;
    for (int r = ty; r < 32; r += 8)
        t[r][tx] = Wl[(size_t)(k0 + r) * N_ + n0 + tx];
    __syncthreads();
    for (int r = ty; r < 32; r += 8) {
        __half hi, lo; h2split(t[tx][r], hi, lo);
        size_t base = (size_t)(n0 + r) * 2 * K_ + k0 + tx;
        Wsl[base] = hi; Wsl[base + K_] = lo;
    }
}

// ---------------- fp16-split wmma GEMM ----------------
// C[M,N_] = A[M,K_] @ Bt[N_,K_]^T + bias, via AhBh + AlBh + AhBl
// A: [M][2K_] (hi|lo), B: [N_][2K_] (hi|lo)
#define SROW 40                 // padded smem row stride (halves); 80B, mult of 16B
#define TILE_H (128 * SROW)     // halves per tensor per stage

template<int GELU, int SPLIT>
__global__ void __launch_bounds__(256) hgemm_kernel(
    const __half* __restrict__ A, const __half* __restrict__ B,
    const float* __restrict__ bias, float* __restrict__ Cout,
    __half* __restrict__ Cs, int N_, int K_)
{
    __shared__ __align__(16) __half sm[4 * TILE_H];  // 2 stages x (A,B) = 40960 B
    int tid = threadIdx.x, wid = tid >> 5, lane = tid & 31;
    const int lda = 2 * K_;
    const int nk = K_ >> 5;
    const int C = 3 * nk;
    const __half* Ab = A + (size_t)(blockIdx.y * 128) * lda;
    const __half* Bb = B + (size_t)(blockIdx.x * 128) * lda;

    auto load_stage = [&](int stg, int chunk) {
        int aoff, boff;
        if (chunk < nk)          { aoff = chunk << 5;                boff = aoff; }
        else if (chunk < 2 * nk) { aoff = K_ + ((chunk - nk) << 5);  boff = (chunk - nk) << 5; }
        else                     { aoff = (chunk - 2 * nk) << 5;     boff = K_ + ((chunk - 2 * nk) << 5); }
        __half* as = sm + stg * 2 * TILE_H;
        __half* bs = as + TILE_H;
        for (int t = tid; t < 512; t += 256) {
            int row = t >> 2, seg = t & 3;
            __pipeline_memcpy_async(&as[row * SROW + seg * 8],
                                    Ab + (size_t)row * lda + aoff + seg * 8, 16);
            __pipeline_memcpy_async(&bs[row * SROW + seg * 8],
                                    Bb + (size_t)row * lda + boff + seg * 8, 16);
        }
        __pipeline_commit();
    };

    wmma::fragment<wmma::accumulator, 16, 16, 16, float> acc[4][2];
    #pragma unroll
    for (int mi = 0; mi < 4; mi++)
        #pragma unroll
        for (int ni = 0; ni < 2; ni++)
            wmma::fill_fragment(acc[mi][ni], 0.f);

    const int wm = (wid >> 2) * 64;   // 0 / 64
    const int wn = (wid & 3) * 32;    // 0..96

    load_stage(0, 0);
    load_stage(1, 1);

    for (int c = 0; c < C; c++) {
        __pipeline_wait_prior(c + 1 < C ? 1 : 0);
        __syncthreads();
        const __half* as = sm + (c & 1) * 2 * TILE_H;
        const __half* bs = as + TILE_H;
        #pragma unroll
        for (int ks = 0; ks < 2; ks++) {
            wmma::fragment<wmma::matrix_b, 16, 16, 16, __half, wmma::col_major> bf[2];
            #pragma unroll
            for (int ni = 0; ni < 2; ni++)
                wmma::load_matrix_sync(bf[ni], &bs[(wn + ni * 16) * SROW + ks * 16], SROW);
            #pragma unroll
            for (int mi = 0; mi < 4; mi++) {
                wmma::fragment<wmma::matrix_a, 16, 16, 16, __half, wmma::row_major> af;
                wmma::load_matrix_sync(af, &as[(wm + mi * 16) * SROW + ks * 16], SROW);
                wmma::mma_sync(acc[mi][0], af, bf[0], acc[mi][0]);
                wmma::mma_sync(acc[mi][1], af, bf[1], acc[mi][1]);
            }
        }
        __syncthreads();
        if (c + 2 < C) load_stage(c & 1, c + 2);
    }

    // epilogue: stage each 16x16 fragment through per-warp smem, fuse bias/gelu/split
    float* esm = reinterpret_cast<float*>(sm) + wid * 320;   // 16 x 20 floats per warp
    const int gr = blockIdx.y * 128 + wm;
    const int gc = blockIdx.x * 128 + wn;
    const int er = lane >> 1;            // 0..15
    const int ec = (lane & 1) * 8;       // 0 / 8
    #pragma unroll
    for (int mi = 0; mi < 4; mi++) {
        #pragma unroll
        for (int ni = 0; ni < 2; ni++) {
            wmma::store_matrix_sync(esm, acc[mi][ni], 20, wmma::mem_row_major);
            __syncwarp();
            int row = gr + mi * 16 + er;
            int colb = gc + ni * 16 + ec;
            #pragma unroll
            for (int e = 0; e < 8; e += 2) {
                int col = colb + e;
                float v0 = esm[er * 20 + ec + e]     + bias[col];
                float v1 = esm[er * 20 + ec + e + 1] + bias[col + 1];
                if (GELU) {
                    float i0 = 0.7978845608028654f * (v0 + 0.044715f * v0 * v0 * v0);
                    float i1 = 0.7978845608028654f * (v1 + 0.044715f * v1 * v1 * v1);
                    v0 = 0.5f * v0 * (1.f + tanhf(i0));
                    v1 = 0.5f * v1 * (1.f + tanhf(i1));
                }
                if (SPLIT) {
                    __half h0, l0, h1, l1;
                    h2split(v0, h0, l0); h2split(v1, h1, l1);
                    size_t base = (size_t)row * 2 * N_ + col;
                    *(__half2*)&Cs[base]      = __halves2half2(h0, h1);
                    *(__half2*)&Cs[base + N_] = __halves2half2(l0, l1);
                } else {
                    *(float2*)&Cout[(size_t)row * N_ + col] = make_float2(v0, v1);
                }
            }
            __syncwarp();
        }
    }
}

// ---------------- attention (fp32, writes fp16 split) ----------------
#define ACHUNK 64
__global__ void __launch_bounds__(224) attention_kernel(const float* __restrict__ qkv,
                                                        __half* __restrict__ ats)
{
    __shared__ float Ks[ACHUNK][HD];
    __shared__ float Vs[ACHUNK][HD];
    int b = blockIdx.x / HEADS, hh = blockIdx.x % HEADS;
    int tid = threadIdx.x;
    const size_t base = (size_t)b * SEQL * (3 * DIM);
    float q[HD], o[HD];
    float m = -1e30f, l = 0.f;
    if (tid < SEQL) {
        const float* qp = qkv + base + (size_t)tid * (3 * DIM) + hh * HD;
        #pragma unroll
        for (int d = 0; d < HD; d++) { q[d] = qp[d]; o[d] = 0.f; }
    }
    for (int kc = 0; kc < SEQL; kc += ACHUNK) {
        int len = min(ACHUNK, SEQL - kc);
        for (int i = tid; i < len * HD; i += 224) {
            int kr = i / HD, d = i - kr * HD;
            size_t src = base + (size_t)(kc + kr) * (3 * DIM) + hh * HD + d;
            Ks[kr][d] = qkv[src + DIM];
            Vs[kr][d] = qkv[src + 2 * DIM];
        }
        __syncthreads();
        if (tid < SEQL) {
            for (int k = 0; k < len; k++) {
                float s = 0.f;
                #pragma unroll
                for (int d = 0; d < HD; d++) s = fmaf(q[d], Ks[k][d], s);
                s *= 0.125f;
                if (s > m) {
                    float corr = __expf(m - s);
                    l *= corr;
                    #pragma unroll
                    for (int d = 0; d < HD; d++) o[d] *= corr;
                    m = s;
                }
                float p = __expf(s - m);
                l += p;
                #pragma unroll
                for (int d = 0; d < HD; d++) o[d] = fmaf(p, Vs[k][d], o[d]);
            }
        }
        __syncthreads();
    }
    if (tid < SEQL) {
        float inv = 1.f / l;
        size_t op = ((size_t)(b * SEQL + tid)) * 2 * DIM + hh * HD;
        #pragma unroll
        for (int d = 0; d < HD; d++) {
            __half hi, lo; h2split(o[d] * inv, hi, lo);
            ats[op + d] = hi; ats[op + d + DIM] = lo;
        }
    }
}

// ---------------- residual + LN (fp32 h, fp16 split hs) ----------------
__global__ void __launch_bounds__(256) add_ln_kernel(float* __restrict__ h, const float* __restrict__ y,
                                                     const float* __restrict__ sc, const float* __restrict__ bb,
                                                     __half* __restrict__ hs)
{
    __shared__ float red1[8], red2[8];
    __shared__ float smean, srstd;
    int tok = blockIdx.x, tid = threadIdx.x;
    const size_t off = (size_t)tok * DIM;
    float v[3];
    #pragma unroll
    for (int i = 0; i < 3; i++) {
        int c = tid + i * 256;
        v[i] = h[off + c] + y[off + c];
    }
    float sum = v[0] + v[1] + v[2];
    #pragma unroll
    for (int o = 16; o > 0; o >>= 1) sum += __shfl_xor_sync(0xffffffff, sum, o);
    if ((tid & 31) == 0) red1[tid >> 5] = sum;
    __syncthreads();
    if (tid == 0) {
        float x = 0.f;
        #pragma unroll
        for (int i = 0; i < 8; i++) x += red1[i];
        smean = x * (1.f / DIM);
    }
    __syncthreads();
    float mean = smean, sq = 0.f;
    #pragma unroll
    for (int i = 0; i < 3; i++) { float d = v[i] - mean; sq += d * d; }
    #pragma unroll
    for (int o = 16; o > 0; o >>= 1) sq += __shfl_xor_sync(0xffffffff, sq, o);
    if ((tid & 31) == 0) red2[tid >> 5] = sq;
    __syncthreads();
    if (tid == 0) {
        float x = 0.f;
        #pragma unroll
        for (int i = 0; i < 8; i++) x += red2[i];
        srstd = rsqrtf(x * (1.f / DIM) + 1e-5f);
    }
    __syncthreads();
    float rstd = srstd;
    #pragma unroll
    for (int i = 0; i < 3; i++) {
        int c = tid + i * 256;
        float r = (v[i] - mean) * rstd * sc[c] + bb[c];
        h[off + c] = r;
        __half hi, lo; h2split(r, hi, lo);
        size_t base = off * 2 + c;
        hs[base] = hi; hs[base + DIM] = lo;
    }
}

__global__ void copyout_kernel(const float* __restrict__ h, float* __restrict__ out)
{
    int idx = blockIdx.x * blockDim.x + threadIdx.x;
    if (idx < MTOK * DIM) out[idx] = h[idx];
}

__global__ void __launch_bounds__(256) head_kernel(const float* __restrict__ h, const float* __restrict__ patch,
                                                   const float* __restrict__ rep_w, const float* __restrict__ rep_b,
                                                   float* __restrict__ outq)
{
    __shared__ int cnt[SEQL];
    __shared__ int csum[SEQL];
    __shared__ int src[MAXSEQ];
    int b = blockIdx.x, tid = threadIdx.x;
    for (int s = tid; s < SEQL; s += 256) {
        const float* hr = h + ((size_t)(b * SEQL + s)) * DIM;
        float acc[MAXREP];
        #pragma unroll
        for (int j = 0; j < MAXREP; j++) acc[j] = rep_b[j];
        for (int kk = 0; kk < DIM; kk++) {
            float hv = hr[kk];
            const float* wr = rep_w + kk * MAXREP;
            #pragma unroll
            for (int j = 0; j < MAXREP; j++) acc[j] = fmaf(hv, wr[j], acc[j]);
        }
        int bi = 0; float bv = acc[0];
        #pragma unroll
        for (int j = 1; j < MAXREP; j++) if (acc[j] > bv) { bv = acc[j]; bi = j; }
        cnt[s] = bi;
    }
    __syncthreads();
    if (tid == 0) {
        int r = 0;
        for (int i = 0; i < SEQL; i++) { r += cnt[i]; csum[i] = r; }
    }
    __syncthreads();
    int total = csum[SEQL - 1];
    if (tid < MAXSEQ) {
        int t = tid, idx = SEQL;
        for (int j = 0; j < SEQL; j++) if (csum[j] > t) { idx = j; break; }
        src[t] = (t < total) ? min(idx, SEQL - 1) : -1;
    }
    __syncthreads();
    for (int i = tid; i < MAXSEQ * DIM; i += 256) {
        int t = i / DIM, d = i - t * DIM;
        int si = src[t];
        float v = (si >= 0) ? patch[((size_t)(b * SEQL + si)) * DIM + d] : 0.f;
        outq[((size_t)(b * MAXSEQ + t)) * DIM + d] = v;
    }
}

// ---------------- launch ----------------
extern "C" void kernel_launch(void* const* d_in, const int* in_sizes, int n_in,
                              void* d_out, int out_size)
{
    const float* x       = (const float*)d_in[0];
    const float* patch_w = (const float*)d_in[1];
    const float* patch_b = (const float*)d_in[2];
    const float* pos     = (const float*)d_in[3];
    const float* Wqkv    = (const float*)d_in[4];
    const float* bqkv    = (const float*)d_in[5];
    const float* Wo      = (const float*)d_in[6];
    const float* bo      = (const float*)d_in[7];
    const float* ln1_s   = (const float*)d_in[8];
    const float* ln1_b   = (const float*)d_in[9];
    const float* W1      = (const float*)d_in[10];
    const float* b1      = (const float*)d_in[11];
    const float* W2      = (const float*)d_in[12];
    const float* b2      = (const float*)d_in[13];
    const float* ln2_s   = (const float*)d_in[14];
    const float* ln2_b   = (const float*)d_in[15];
    const float* rep_w   = (const float*)d_in[16];
    const float* rep_b   = (const float*)d_in[17];
    float* out = (float*)d_out;

    float *patch, *h, *qkv, *tmp;
    __half *xs, *hs, *ats, *ffs, *pws, *wqs, *wos, *w1s, *w2s;
    cudaGetSymbolAddress((void**)&patch, g_patch);
    cudaGetSymbolAddress((void**)&h,     g_h);
    cudaGetSymbolAddress((void**)&qkv,   g_qkv);
    cudaGetSymbolAddress((void**)&tmp,   g_tmp);
    cudaGetSymbolAddress((void**)&xs,    g_xs);
    cudaGetSymbolAddress((void**)&hs,    g_hs);
    cudaGetSymbolAddress((void**)&ats,   g_ats);
    cudaGetSymbolAddress((void**)&ffs,   g_ffs);
    cudaGetSymbolAddress((void**)&pws,   g_pws);
    cudaGetSymbolAddress((void**)&wqs,   g_wqs);
    cudaGetSymbolAddress((void**)&wos,   g_wos);
    cudaGetSymbolAddress((void**)&w1s,   g_w1s);
    cudaGetSymbolAddress((void**)&w2s,   g_w2s);

    const int EL = MTOK * DIM;
    const int TB = 256;
    dim3 wb(32, 8);
    wsplit_kernel<<<dim3(DIM / 32, DIM / 32, 1), wb>>>(patch_w, pws, DIM, DIM);
    wsplit_kernel<<<dim3(3 * DIM / 32, DIM / 32, DEPTH), wb>>>(Wqkv, wqs, DIM, 3 * DIM);
    wsplit_kernel<<<dim3(DIM / 32, DIM / 32, DEPTH), wb>>>(Wo, wos, DIM, DIM);
    wsplit_kernel<<<dim3(DFF / 32, DIM / 32, DEPTH), wb>>>(W1, w1s, DIM, DFF);
    wsplit_kernel<<<dim3(DIM / 32, DFF / 32, DEPTH), wb>>>(W2, w2s, DFF, DIM);

    patchify_kernel<<<(EL + TB - 1) / TB, TB>>>(x, xs);
    hgemm_kernel<0, 0><<<dim3(DIM / 128, MTOK / 128), 256>>>(
        xs, pws, patch_b, patch, nullptr, DIM, DIM);
    addpos_kernel<<<(EL + TB - 1) / TB, TB>>>(patch, pos, h, hs);

    for (int l = 0; l < DEPTH; l++) {
        hgemm_kernel<0, 0><<<dim3(3 * DIM / 128, MTOK / 128), 256>>>(
            hs, wqs + (size_t)l * 3 * DIM * 2 * DIM, bqkv + (size_t)l * 3 * DIM,
            qkv, nullptr, 3 * DIM, DIM);
        attention_kernel<<<BATCH * HEADS, 224>>>(qkv, ats);
        hgemm_kernel<0, 0><<<dim3(DIM / 128, MTOK / 128), 256>>>(
            ats, wos + (size_t)l * DIM * 2 * DIM, bo + (size_t)l * DIM,
            tmp, nullptr, DIM, DIM);
        add_ln_kernel<<<MTOK, 256>>>(h, tmp, ln1_s + (size_t)l * DIM, ln1_b + (size_t)l * DIM, hs);
        hgemm_kernel<1, 1><<<dim3(DFF / 128, MTOK / 128), 256>>>(
            hs, w1s + (size_t)l * DFF * 2 * DIM, b1 + (size_t)l * DFF,
            nullptr, ffs, DFF, DIM);
        hgemm_kernel<0, 0><<<dim3(DIM / 128, MTOK / 128), 256>>>(
            ffs, w2s + (size_t)l * DIM * 2 * DFF, b2 + (size_t)l * DIM,
            tmp, nullptr, DIM, DFF);
        add_ln_kernel<<<MTOK, 256>>>(h, tmp, ln2_s + (size_t)l * DIM, ln2_b + (size_t)l * DIM, hs);
    }

    copyout_kernel<<<(EL + TB - 1) / TB, TB>>>(h, out);
    head_kernel<<<BATCH, 256>>>(h, patch, rep_w, rep_b, out + (size_t)MTOK * DIM);
}